// round 7
// baseline (speedup 1.0000x reference)
#include <cuda_runtime.h>
#include <cuda_bf16.h>
#include <cuda_fp8.h>
#include <cstdint>

#define Nn 4096
#define Cc 1000
#define Aa 2048
#define Cpad 1024

#define BM 128
#define BN 128
#define NKT (Aa / 32)              // 64 k-steps of 32 elems

// bf16 tile: 128 rows x 64B (32 bf16) = 8KB ; fp8 tile: 128 rows x 32B = 4KB
#define T16 8192
#define T8  4096
#define STAGE_L (2 * T16)          // Fhi, Whi
#define STAGE_8 (4 * T8)           // A0,A1,B0,B1
#define NST 4
#define SMEM_L (NST * STAGE_L)     // 64KB
#define SMEM_8 (NST * STAGE_8)     // 64KB

// fp8 scales (descale products: corr 2^-27, S 2^-23)
#define SC_F    64.f
#define SC_FLO  32768.f            // 2^15
#define SC_W    4096.f             // 2^12
#define SC_WLO  2097152.f          // 2^21
#define SC_C    256.f              // 2^8
#define SC_W2   32768.f            // 2^15
#define SC_G    2048.f             // 2^11
#define DS_CORR (1.f / 134217728.f)  // 2^-27
#define DS_S    (1.f / 8388608.f)    // 2^-23

// -------- device scratch --------
__device__ __nv_bfloat16 g_Fhi[(size_t)Nn * Aa];
__device__ __nv_bfloat16 g_Whi[(size_t)Cpad * Aa];
__device__ uint8_t g_F8  [(size_t)Nn * Aa];
__device__ uint8_t g_Flo8[(size_t)Nn * Aa];
__device__ uint8_t g_C8  [(size_t)Nn * Aa];
__device__ uint8_t g_G8  [(size_t)Nn * Aa];   // -2*cv*Wy scaled
__device__ uint8_t g_W8  [(size_t)Cpad * Aa];
__device__ uint8_t g_Wlo8[(size_t)Cpad * Aa];
__device__ uint8_t g_W28 [(size_t)Cpad * Aa];
__device__ float g_tmp[(size_t)Nn * Cpad];    // corr * 2^-27
__device__ float g_t3[Nn];
__device__ float g_aug[(size_t)Nn * Cc];
__device__ float g_nll[Nn];

// -------- helpers --------
__device__ __forceinline__ uint32_t smem_u32(const void* p) {
    return (uint32_t)__cvta_generic_to_shared(const_cast<void*>(p));
}
__device__ __forceinline__ void cp16(uint32_t s, const void* g) {
    asm volatile("cp.async.cg.shared.global [%0], [%1], 16;" :: "r"(s), "l"(g));
}
__device__ __forceinline__ void cp_commit() {
    asm volatile("cp.async.commit_group;" ::: "memory");
}
__device__ __forceinline__ void ldsm4(uint32_t* r, uint32_t addr) {
    asm volatile("ldmatrix.sync.aligned.m8n8.x4.shared.b16 {%0,%1,%2,%3}, [%4];"
                 : "=r"(r[0]), "=r"(r[1]), "=r"(r[2]), "=r"(r[3]) : "r"(addr));
}
__device__ __forceinline__ void mma_bf16(float* d, const uint32_t* a, uint32_t b0, uint32_t b1) {
    asm volatile(
        "mma.sync.aligned.m16n8k16.row.col.f32.bf16.bf16.f32 "
        "{%0,%1,%2,%3}, {%4,%5,%6,%7}, {%8,%9}, {%0,%1,%2,%3};"
        : "+f"(d[0]), "+f"(d[1]), "+f"(d[2]), "+f"(d[3])
        : "r"(a[0]), "r"(a[1]), "r"(a[2]), "r"(a[3]), "r"(b0), "r"(b1));
}
__device__ __forceinline__ void mma_fp8(float* d, const uint32_t* a, uint32_t b0, uint32_t b1) {
    asm volatile(
        "mma.sync.aligned.m16n8k32.row.col.f32.e4m3.e4m3.f32 "
        "{%0,%1,%2,%3}, {%4,%5,%6,%7}, {%8,%9}, {%0,%1,%2,%3};"
        : "+f"(d[0]), "+f"(d[1]), "+f"(d[2]), "+f"(d[3])
        : "r"(a[0]), "r"(a[1]), "r"(a[2]), "r"(a[3]), "r"(b0), "r"(b1));
}
__device__ __forceinline__ int load_label(const int* labels, int n) {
    int lab = labels[n];
    return lab < 0 ? 0 : (lab >= Cc ? Cc - 1 : lab);
}
// bf16 tile swizzle (64B rows, 4x16B chunks)
__device__ __forceinline__ uint32_t tswz(int row, int c16) {
    return (uint32_t)(row * 64 + ((c16 ^ ((row >> 1) & 3)) << 4));
}
// fp8 tile swizzle (32B rows, 2x16B chunks)
__device__ __forceinline__ uint32_t t8swz(int row, int c16) {
    return (uint32_t)(row * 32 + ((c16 ^ (row & 1)) << 4));
}
__device__ __forceinline__ uint32_t bf2(float a, float b) {
    __nv_bfloat162 h = __floats2bfloat162_rn(a, b);
    return *(uint32_t*)&h;
}
__device__ __forceinline__ uint32_t fp8x4(float a, float b, float c, float d) {
    uint32_t r = (uint32_t)__nv_cvt_float_to_fp8(a, __NV_SATFINITE, __NV_E4M3);
    r |= (uint32_t)__nv_cvt_float_to_fp8(b, __NV_SATFINITE, __NV_E4M3) << 8;
    r |= (uint32_t)__nv_cvt_float_to_fp8(c, __NV_SATFINITE, __NV_E4M3) << 16;
    r |= (uint32_t)__nv_cvt_float_to_fp8(d, __NV_SATFINITE, __NV_E4M3) << 24;
    return r;
}

// ---------------- prep ----------------
__global__ void prep_all(const float* __restrict__ F, const float* __restrict__ CV,
                         const int* __restrict__ labels, const float* __restrict__ W) {
    const int b = blockIdx.x;
    const int tid = threadIdx.x;
    if (b < Cpad) {
        const int c = b;
        uint32_t* wh = (uint32_t*)(g_Whi + (size_t)c * Aa);   // 2 bf16 per u32
        uint32_t* w8 = (uint32_t*)(g_W8 + (size_t)c * Aa);    // 4 fp8 per u32
        uint32_t* wl8 = (uint32_t*)(g_Wlo8 + (size_t)c * Aa);
        uint32_t* w28 = (uint32_t*)(g_W28 + (size_t)c * Aa);
        if (c >= Cc) {
            for (int q = tid; q < Aa / 4; q += 256) {
                wh[q * 2] = 0u; wh[q * 2 + 1] = 0u;
                w8[q] = 0u; wl8[q] = 0u; w28[q] = 0u;
            }
            return;
        }
        const float4* wrow = (const float4*)(W + (size_t)c * Aa);
        for (int q = tid; q < Aa / 4; q += 256) {
            float4 w = wrow[q];
            __nv_bfloat16 h0 = __float2bfloat16(w.x), h1 = __float2bfloat16(w.y);
            __nv_bfloat16 h2 = __float2bfloat16(w.z), h3 = __float2bfloat16(w.w);
            float l0 = w.x - __bfloat162float(h0), l1 = w.y - __bfloat162float(h1);
            float l2 = w.z - __bfloat162float(h2), l3 = w.w - __bfloat162float(h3);
            wh[q * 2]     = bf2(w.x, w.y);
            wh[q * 2 + 1] = bf2(w.z, w.w);
            w8[q]  = fp8x4(w.x * SC_W,  w.y * SC_W,  w.z * SC_W,  w.w * SC_W);
            wl8[q] = fp8x4(l0 * SC_WLO, l1 * SC_WLO, l2 * SC_WLO, l3 * SC_WLO);
            w28[q] = fp8x4(w.x * w.x * SC_W2, w.y * w.y * SC_W2,
                           w.z * w.z * SC_W2, w.w * w.w * SC_W2);
        }
    } else {
        const int n = b - Cpad;
        const int lab = load_label(labels, n);
        const float4* frow = (const float4*)(F  + (size_t)n * Aa);
        const float4* crow = (const float4*)(CV + (size_t)n * Aa);
        const float4* wrow = (const float4*)(W  + (size_t)lab * Aa);
        uint32_t* fh = (uint32_t*)(g_Fhi + (size_t)n * Aa);
        uint32_t* f8 = (uint32_t*)(g_F8 + (size_t)n * Aa);
        uint32_t* fl8 = (uint32_t*)(g_Flo8 + (size_t)n * Aa);
        uint32_t* c8 = (uint32_t*)(g_C8 + (size_t)n * Aa);
        uint32_t* g8 = (uint32_t*)(g_G8 + (size_t)n * Aa);

        float t3 = 0.f;
        for (int q = tid; q < Aa / 4; q += 256) {
            float4 f = frow[q];
            float4 cv = crow[q];
            float4 wy = wrow[q];
            __nv_bfloat16 h0 = __float2bfloat16(f.x), h1 = __float2bfloat16(f.y);
            __nv_bfloat16 h2 = __float2bfloat16(f.z), h3 = __float2bfloat16(f.w);
            float l0 = f.x - __bfloat162float(h0), l1 = f.y - __bfloat162float(h1);
            float l2 = f.z - __bfloat162float(h2), l3 = f.w - __bfloat162float(h3);
            fh[q * 2]     = bf2(f.x, f.y);
            fh[q * 2 + 1] = bf2(f.z, f.w);
            f8[q]  = fp8x4(f.x * SC_F, f.y * SC_F, f.z * SC_F, f.w * SC_F);
            fl8[q] = fp8x4(l0 * SC_FLO, l1 * SC_FLO, l2 * SC_FLO, l3 * SC_FLO);
            c8[q]  = fp8x4(cv.x * SC_C, cv.y * SC_C, cv.z * SC_C, cv.w * SC_C);
            float gx = cv.x * wy.x, gy = cv.y * wy.y, gz = cv.z * wy.z, gw = cv.w * wy.w;
            g8[q] = fp8x4(-2.f * gx * SC_G, -2.f * gy * SC_G,
                          -2.f * gz * SC_G, -2.f * gw * SC_G);
            t3 += gx * wy.x + gy * wy.y + gz * wy.z + gw * wy.w;
        }
        for (int o = 16; o; o >>= 1) t3 += __shfl_xor_sync(~0u, t3, o);
        __shared__ float ws[8];
        if ((tid & 31) == 0) ws[tid >> 5] = t3;
        __syncthreads();
        if (tid == 0) {
            float s = 0.f;
            for (int i = 0; i < 8; i++) s += ws[i];
            g_t3[n] = s;
        }
    }
}

// common prologue pieces
#define GEMM_IDS                                                              \
    const int tid = threadIdx.x;                                              \
    const int lane = tid & 31;                                                \
    const int wid = tid >> 5;                                                 \
    const int warp_m = wid >> 2;                                              \
    const int warp_n = wid & 3;                                               \
    const int bm = blockIdx.y * BM;                                           \
    const int bn = blockIdx.x * BN;                                           \
    const int lr16 = lane & 15;                                               \
    const int lkhalf = lane >> 4;

#define WAIT_PIPE(kt)                                                         \
    if ((kt) < NKT - 2)      { asm volatile("cp.async.wait_group 2;" ::: "memory"); } \
    else if ((kt) == NKT - 2){ asm volatile("cp.async.wait_group 1;" ::: "memory"); } \
    else                     { asm volatile("cp.async.wait_group 0;" ::: "memory"); }

// ---------------- gemmL: main logits = Fhi . Whi (bf16) ----------------
__global__ __launch_bounds__(256, 2)
void gemmL(const float* __restrict__ bias, float* __restrict__ logits_out)
{
    extern __shared__ char smem[];
    const uint32_t sbase = smem_u32(smem);
    GEMM_IDS
    const char* mpa = (const char*)g_Fhi + (size_t)bm * 4096;
    const char* mpb = (const char*)g_Whi + (size_t)bn * 4096;

    const int lrow = tid >> 2;
    const int lc16 = tid & 3;
    const uint32_t so0 = tswz(lrow, lc16);
    const uint32_t so1 = tswz(lrow + 64, lc16);
    const size_t go0 = (size_t)lrow * 4096 + lc16 * 16;
    const size_t go1 = go0 + (size_t)64 * 4096;

#define ISSUE_L(KT, S)                                                        \
    do {                                                                      \
        const size_t kb = (size_t)(KT) * 64;                                  \
        const uint32_t st_ = sbase + (uint32_t)(S) * STAGE_L;                 \
        cp16(st_ + so0, mpa + go0 + kb);                                      \
        cp16(st_ + so1, mpa + go1 + kb);                                      \
        cp16(st_ + T16 + so0, mpb + go0 + kb);                                \
        cp16(st_ + T16 + so1, mpb + go1 + kb);                                \
        cp_commit();                                                          \
    } while (0)

    float acc[4][4][4];
#pragma unroll
    for (int i = 0; i < 4; i++)
#pragma unroll
        for (int j = 0; j < 4; j++)
#pragma unroll
            for (int e = 0; e < 4; e++) acc[i][j][e] = 0.f;

    ISSUE_L(0, 0); ISSUE_L(1, 1); ISSUE_L(2, 2);

    for (int kt = 0; kt < NKT; kt++) {
        WAIT_PIPE(kt)
        __syncthreads();
        if (kt + 3 < NKT) ISSUE_L(kt + 3, (kt + 3) & 3);
        const uint32_t st = sbase + (uint32_t)(kt & 3) * STAGE_L;
#pragma unroll
        for (int k16 = 0; k16 < 2; k16++) {
            uint32_t bfr[2][4];
#pragma unroll
            for (int np = 0; np < 2; np++)
                ldsm4(bfr[np], st + T16 + tswz(warp_n * 32 + np * 16 + lr16, k16 * 2 + lkhalf));
#pragma unroll
            for (int mt = 0; mt < 4; mt++) {
                uint32_t af[4];
                ldsm4(af, st + tswz(warp_m * 64 + mt * 16 + lr16, k16 * 2 + lkhalf));
#pragma unroll
                for (int nt = 0; nt < 4; nt++) {
                    const int np = nt >> 1, sel = nt & 1;
                    mma_bf16(acc[mt][nt], af, bfr[np][sel], bfr[np][sel + 2]);
                }
            }
        }
    }
#undef ISSUE_L

    // epilogue: logits = acc + corr*2^-27 + bias ; aug = logits + augS
    const int r0 = lane >> 2;
    const int cq = (lane & 3) * 2;
#pragma unroll
    for (int mt = 0; mt < 4; mt++) {
        const int n0 = bm + warp_m * 64 + mt * 16 + r0;
        const int n1 = n0 + 8;
        float* lr0 = logits_out + (size_t)n0 * Cc;
        float* lr1 = logits_out + (size_t)n1 * Cc;
        float* ar0 = g_aug + (size_t)n0 * Cc;
        float* ar1 = g_aug + (size_t)n1 * Cc;
        const float* tp0 = g_tmp + (size_t)n0 * Cpad;
        const float* tp1 = g_tmp + (size_t)n1 * Cpad;
#pragma unroll
        for (int nt = 0; nt < 4; nt++) {
            const int c = bn + warp_n * 32 + nt * 8 + cq;
            if (c < Cc) {
                const float2 bv = *(const float2*)(bias + c);
                const float2 c0 = *(const float2*)(tp0 + c);
                const float2 c1 = *(const float2*)(tp1 + c);
                const float2 s0 = *(const float2*)(ar0 + c);
                const float2 s1 = *(const float2*)(ar1 + c);
                const float* L = acc[mt][nt];
                const float l00 = L[0] + c0.x * DS_CORR + bv.x;
                const float l01 = L[1] + c0.y * DS_CORR + bv.y;
                const float l10 = L[2] + c1.x * DS_CORR + bv.x;
                const float l11 = L[3] + c1.y * DS_CORR + bv.y;
                lr0[c] = l00; lr0[c + 1] = l01;     // logits_out only 4B aligned
                lr1[c] = l10; lr1[c + 1] = l11;
                *(float2*)(ar0 + c) = make_float2(l00 + s0.x, l01 + s0.y);
                *(float2*)(ar1 + c) = make_float2(l10 + s1.x, l11 + s1.y);
            }
        }
    }
}

// ---------------- fp8 GEMM skeleton ----------------
#define FP8_BODY(A0, A1, B0, B1)                                              \
    extern __shared__ char smem[];                                            \
    const uint32_t sbase = smem_u32(smem);                                    \
    GEMM_IDS                                                                  \
    const char* mp[4];                                                        \
    mp[0] = (const char*)(A0) + (size_t)bm * 2048;                            \
    mp[1] = (const char*)(A1) + (size_t)bm * 2048;                            \
    mp[2] = (const char*)(B0) + (size_t)bn * 2048;                            \
    mp[3] = (const char*)(B1) + (size_t)bn * 2048;                            \
    const int lrow = tid >> 1;                                                \
    const int lchk = tid & 1;                                                 \
    const uint32_t so8 = t8swz(lrow, lchk);                                   \
    const size_t go8 = (size_t)lrow * 2048 + lchk * 16;                       \
    float acc[4][4][4];                                                       \
    _Pragma("unroll")                                                         \
    for (int i = 0; i < 4; i++)                                               \
        _Pragma("unroll")                                                     \
        for (int j = 0; j < 4; j++)                                           \
            _Pragma("unroll")                                                 \
            for (int e = 0; e < 4; e++) acc[i][j][e] = 0.f;                   \
    ISSUE_8(0, 0); ISSUE_8(1, 1); ISSUE_8(2, 2);                              \
    for (int kt = 0; kt < NKT; kt++) {                                        \
        WAIT_PIPE(kt)                                                         \
        __syncthreads();                                                      \
        if (kt + 3 < NKT) ISSUE_8(kt + 3, (kt + 3) & 3);                      \
        const uint32_t st = sbase + (uint32_t)(kt & 3) * STAGE_8;             \
        uint32_t b0f[2][4], b1f[2][4];                                        \
        _Pragma("unroll")                                                     \
        for (int np = 0; np < 2; np++) {                                      \
            const int r = warp_n * 32 + np * 16 + lr16;                       \
            ldsm4(b0f[np], st + 2 * T8 + t8swz(r, lkhalf));                   \
            ldsm4(b1f[np], st + 3 * T8 + t8swz(r, lkhalf));                   \
        }                                                                     \
        _Pragma("unroll")                                                     \
        for (int mt = 0; mt < 4; mt++) {                                      \
            uint32_t a0f[4], a1f[4];                                          \
            const int r = warp_m * 64 + mt * 16 + lr16;                       \
            ldsm4(a0f, st + 0 * T8 + t8swz(r, lkhalf));                       \
            ldsm4(a1f, st + 1 * T8 + t8swz(r, lkhalf));                       \
            _Pragma("unroll")                                                 \
            for (int nt = 0; nt < 4; nt++) {                                  \
                const int np = nt >> 1, sel = nt & 1;                         \
                mma_fp8(acc[mt][nt], a0f, b0f[np][sel], b0f[np][sel + 2]);    \
                mma_fp8(acc[mt][nt], a1f, b1f[np][sel], b1f[np][sel + 2]);    \
            }                                                                 \
        }                                                                     \
    }

#define ISSUE_8(KT, S)                                                        \
    do {                                                                      \
        const size_t kb = (size_t)(KT) * 32;                                  \
        const uint32_t st_ = sbase + (uint32_t)(S) * STAGE_8;                 \
        _Pragma("unroll")                                                     \
        for (int m_ = 0; m_ < 4; m_++)                                        \
            cp16(st_ + m_ * T8 + so8, mp[m_] + go8 + kb);                     \
        cp_commit();                                                          \
    } while (0)

// gemmC: corr = F8.Wlo8 + Flo8.W8  -> g_tmp (raw, descale applied in gemmL)
__global__ __launch_bounds__(256, 2)
void gemmC()
{
    FP8_BODY(g_F8, g_Flo8, g_Wlo8, g_W8)
    const int r0 = lane >> 2;
    const int cq = (lane & 3) * 2;
#pragma unroll
    for (int mt = 0; mt < 4; mt++) {
        const int n0 = bm + warp_m * 64 + mt * 16 + r0;
        float* t0 = g_tmp + (size_t)n0 * Cpad;
        float* t1 = g_tmp + (size_t)(n0 + 8) * Cpad;
#pragma unroll
        for (int nt = 0; nt < 4; nt++) {
            const int c = bn + warp_n * 32 + nt * 8 + cq;
            const float* A = acc[mt][nt];
            *(float2*)(t0 + c) = make_float2(A[0], A[1]);
            *(float2*)(t1 + c) = make_float2(A[2], A[3]);
        }
    }
}

// gemmS: S = C8.W28 + G8.W8 ; g_aug = hr*(S*2^-23 + t3)
__global__ __launch_bounds__(256, 2)
void gemmS(const float* __restrict__ ratio_p)
{
    FP8_BODY(g_C8, g_G8, g_W28, g_W8)
    const float hr = 0.5f * (*ratio_p);
    const int r0 = lane >> 2;
    const int cq = (lane & 3) * 2;
#pragma unroll
    for (int mt = 0; mt < 4; mt++) {
        const int n0 = bm + warp_m * 64 + mt * 16 + r0;
        const int n1 = n0 + 8;
        const float t3a = g_t3[n0];
        const float t3b = g_t3[n1];
        float* a0 = g_aug + (size_t)n0 * Cc;
        float* a1 = g_aug + (size_t)n1 * Cc;
#pragma unroll
        for (int nt = 0; nt < 4; nt++) {
            const int c = bn + warp_n * 32 + nt * 8 + cq;
            if (c < Cc) {
                const float* A = acc[mt][nt];
                *(float2*)(a0 + c) = make_float2(hr * (A[0] * DS_S + t3a),
                                                 hr * (A[1] * DS_S + t3a));
                *(float2*)(a1 + c) = make_float2(hr * (A[2] * DS_S + t3b),
                                                 hr * (A[3] * DS_S + t3b));
            }
        }
    }
}

// ---------------- softmax / NLL (warp per row, register-cached) ----------------
__global__ void softmax_nll_kernel(const int* __restrict__ labels) {
    const int w = threadIdx.x >> 5;
    const int lane = threadIdx.x & 31;
    const int n = blockIdx.x * 8 + w;
    const float4* row4 = (const float4*)(g_aug + (size_t)n * Cc);

    float4 v[8];
#pragma unroll
    for (int j = 0; j < 8; j++) {
        const int idx = lane + 32 * j;
        v[j] = (idx < 250) ? row4[idx] : make_float4(-3.4e38f, -3.4e38f, -3.4e38f, -3.4e38f);
    }
    float mx = -3.4e38f;
#pragma unroll
    for (int j = 0; j < 8; j++)
        mx = fmaxf(mx, fmaxf(fmaxf(v[j].x, v[j].y), fmaxf(v[j].z, v[j].w)));
    for (int o = 16; o; o >>= 1) mx = fmaxf(mx, __shfl_xor_sync(~0u, mx, o));

    float sum = 0.f;
#pragma unroll
    for (int j = 0; j < 8; j++)
        sum += expf(v[j].x - mx) + expf(v[j].y - mx) + expf(v[j].z - mx) + expf(v[j].w - mx);
    for (int o = 16; o; o >>= 1) sum += __shfl_xor_sync(~0u, sum, o);

    if (lane == 0) {
        const int lab = load_label(labels, n);
        const float labv = g_aug[(size_t)n * Cc + lab];
        g_nll[n] = logf(sum) + mx - labv;
    }
}

// ---------------- mean reduce ----------------
__global__ void finalize_kernel(float* __restrict__ out) {
    const int tid = threadIdx.x;
    float s = 0.f;
    for (int i = tid; i < Nn; i += 1024) s += g_nll[i];
    for (int o = 16; o; o >>= 1) s += __shfl_xor_sync(~0u, s, o);
    __shared__ float ws[32];
    if ((tid & 31) == 0) ws[tid >> 5] = s;
    __syncthreads();
    if (tid < 32) {
        float v = ws[tid];
        for (int o = 16; o; o >>= 1) v += __shfl_xor_sync(~0u, v, o);
        if (tid == 0) out[0] = v / (float)Nn;
    }
}

// ---------------- launch ----------------
extern "C" void kernel_launch(void* const* d_in, const int* in_sizes, int n_in,
                              void* d_out, int out_size) {
    const float* F      = (const float*)d_in[0];
    const int*   labels = (const int*)d_in[1];
    const float* CV     = (const float*)d_in[2];
    const float* ratio  = (const float*)d_in[3];
    const float* W      = (const float*)d_in[4];
    const float* bias   = (const float*)d_in[5];
    float* out = (float*)d_out;

    long long logits_off = (long long)out_size - (long long)Nn * Cc;
    if (logits_off < 0) logits_off = 0;
    float* logits_out = out + logits_off;

    static bool attr_set = false;
    if (!attr_set) {
        cudaFuncSetAttribute(gemmL, cudaFuncAttributeMaxDynamicSharedMemorySize, SMEM_L);
        cudaFuncSetAttribute(gemmC, cudaFuncAttributeMaxDynamicSharedMemorySize, SMEM_8);
        cudaFuncSetAttribute(gemmS, cudaFuncAttributeMaxDynamicSharedMemorySize, SMEM_8);
        attr_set = true;
    }

    prep_all<<<Cpad + Nn, 256>>>(F, CV, labels, W);

    dim3 grid(Cpad / BN, Nn / BM);  // 8 x 32 = 256 CTAs
    gemmC<<<grid, 256, SMEM_8>>>();
    gemmS<<<grid, 256, SMEM_8>>>(ratio);
    gemmL<<<grid, 256, SMEM_L>>>(bias, logits_out);

    softmax_nll_kernel<<<Nn / 8, 256>>>(labels);
    finalize_kernel<<<1, 1024>>>(out);
}